// round 1
// baseline (speedup 1.0000x reference)
#include <cuda_runtime.h>
#include <math.h>
#include <stdint.h>

#define C 256
#define BATCH 8
#define NTOK 5376
#define TOT (BATCH*NTOK)   /* 43008 */
#define KINST 100
#define LN_EPS 1e-5f

#define NI_OFF 0
#define SC_OFF 8
#define CL_OFF 808
#define BX_OFF 1608

// ---------------- device scratch (no allocations allowed) ----------------
__device__ float g_flat[TOT*C];
__device__ float g_h0[TOT*C];
__device__ float g_h1[TOT*C];
__device__ float g_logits[TOT];
__device__ float g_vals[BATCH*KINST];
__device__ int   g_idx[BATCH*KINST];
__device__ float g_gath[BATCH*KINST*C];

// ---------------- fused GEMM (X[nrows,256] @ W[256,256] + b) -> LN -> SiLU ----
// 64 rows x 256 cols per block, 256 threads, 8x8 per thread.
// Each warp owns 8 full rows -> LayerNorm via warp shuffles.
__global__ __launch_bounds__(256) void gemm_mlp_ln_silu(
    const float* __restrict__ X, const float* __restrict__ W,
    const float* __restrict__ bias, const float* __restrict__ lng,
    const float* __restrict__ lnb, float* __restrict__ Y, int nrows)
{
    __shared__ float Xs[64*36];     // [row][k], row stride 36 (16B aligned)
    __shared__ float Ws[32*257];    // [k][col], stride 257 avoids conflicts
    const int tid  = threadIdx.x;
    const int lane = tid & 31;
    const int wy   = tid >> 5;      // warp id = row group
    const int row0 = blockIdx.x * 64;

    float acc[8][8];
#pragma unroll
    for (int r = 0; r < 8; r++)
#pragma unroll
        for (int c = 0; c < 8; c++) acc[r][c] = 0.f;

    for (int k0 = 0; k0 < 256; k0 += 32) {
        // X tile: 64 rows x 32 k = 512 float4
#pragma unroll
        for (int j = 0; j < 2; j++) {
            int f = tid + j * 256;
            int r = f >> 3, k4 = f & 7;
            int rg = row0 + r; if (rg >= nrows) rg = nrows - 1;
            float4 v = *(const float4*)(X + (size_t)rg * 256 + k0 + k4 * 4);
            float* d = &Xs[r * 36 + k4 * 4];
            d[0] = v.x; d[1] = v.y; d[2] = v.z; d[3] = v.w;
        }
        // W tile: rows k0..k0+31, all 256 cols (contiguous 8192 floats)
        const float4* W4 = (const float4*)(W + (size_t)k0 * 256);
#pragma unroll
        for (int j = 0; j < 8; j++) {
            int f = tid + j * 256;
            int kk = f >> 6, o4 = f & 63;
            float4 v = W4[f];
            float* d = &Ws[kk * 257 + o4 * 4];
            d[0] = v.x; d[1] = v.y; d[2] = v.z; d[3] = v.w;
        }
        __syncthreads();
#pragma unroll 8
        for (int kk = 0; kk < 32; kk++) {
            float xr[8], wr[8];
#pragma unroll
            for (int r = 0; r < 8; r++) xr[r] = Xs[(wy * 8 + r) * 36 + kk];
#pragma unroll
            for (int c = 0; c < 8; c++) wr[c] = Ws[kk * 257 + lane + c * 32];
#pragma unroll
            for (int r = 0; r < 8; r++)
#pragma unroll
                for (int c = 0; c < 8; c++)
                    acc[r][c] = fmaf(xr[r], wr[c], acc[r][c]);
        }
        __syncthreads();
    }

    float bcol[8], gcol[8], obcol[8];
#pragma unroll
    for (int c = 0; c < 8; c++) {
        int col = lane + c * 32;
        bcol[c] = bias[col]; gcol[c] = lng[col]; obcol[c] = lnb[col];
    }
#pragma unroll
    for (int r = 0; r < 8; r++) {
        int rowg = row0 + wy * 8 + r;
        float s = 0.f, s2 = 0.f;
#pragma unroll
        for (int c = 0; c < 8; c++) {
            float v = acc[r][c] + bcol[c];
            acc[r][c] = v; s += v; s2 += v * v;
        }
#pragma unroll
        for (int o = 16; o > 0; o >>= 1) {
            s  += __shfl_xor_sync(0xffffffffu, s,  o);
            s2 += __shfl_xor_sync(0xffffffffu, s2, o);
        }
        float mean = s * (1.f / 256.f);
        float var  = s2 * (1.f / 256.f) - mean * mean;
        float rs   = rsqrtf(var + LN_EPS);
        if (rowg < nrows) {
#pragma unroll
            for (int c = 0; c < 8; c++) {
                float v = (acc[r][c] - mean) * rs * gcol[c] + obcol[c];
                float y = v / (1.f + expf(-v));      // SiLU
                Y[(size_t)rowg * 256 + lane + c * 32] = y;
            }
        }
    }
}

// ---------------- lateral 1x1 conv + BN ----------------
// out[b, hw, o] = BN( sum_c W[o,c] * x[b,c,hw] ), written into g_flat tokens.
__global__ __launch_bounds__(256) void lateral_kernel(
    const float* __restrict__ x, const float* __restrict__ W, int Cin, int HW,
    const float* __restrict__ bng, const float* __restrict__ bnb,
    const float* __restrict__ bnm, const float* __restrict__ bnv,
    int lvl_off, float* __restrict__ Y)
{
    __shared__ float Xs[32*64];     // [k][row]
    __shared__ float Ws[32*257];    // [k][col(out)]
    const int tid  = threadIdx.x;
    const int lane = tid & 31;
    const int wy   = tid >> 5;
    const int row0 = blockIdx.x * 64;
    const int b    = row0 / HW;     // HW is a multiple of 64 -> whole tile same b
    const int hw0  = row0 % HW;

    float acc[8][8];
#pragma unroll
    for (int r = 0; r < 8; r++)
#pragma unroll
        for (int c = 0; c < 8; c++) acc[r][c] = 0.f;

    for (int k0 = 0; k0 < Cin; k0 += 32) {
        // X tile: (k, row) with row contiguous in gmem
#pragma unroll
        for (int j = 0; j < 2; j++) {
            int f = tid + j * 256;
            int kk = f >> 4, r4 = f & 15;
            float4 v = *(const float4*)(x + ((size_t)b * Cin + k0 + kk) * HW + hw0 + r4 * 4);
            float* d = &Xs[kk * 64 + r4 * 4];
            d[0] = v.x; d[1] = v.y; d[2] = v.z; d[3] = v.w;
        }
        // W tile: W[o][k0..k0+31] -> Ws[kk][o]
#pragma unroll
        for (int j = 0; j < 8; j++) {
            int f = tid + j * 256;
            int o = f >> 3, k4 = f & 7;
            float4 v = *(const float4*)(W + (size_t)o * Cin + k0 + k4 * 4);
            Ws[(k4 * 4 + 0) * 257 + o] = v.x;
            Ws[(k4 * 4 + 1) * 257 + o] = v.y;
            Ws[(k4 * 4 + 2) * 257 + o] = v.z;
            Ws[(k4 * 4 + 3) * 257 + o] = v.w;
        }
        __syncthreads();
#pragma unroll 8
        for (int kk = 0; kk < 32; kk++) {
            float xr[8], wr[8];
#pragma unroll
            for (int r = 0; r < 8; r++) xr[r] = Xs[kk * 64 + wy * 8 + r];
#pragma unroll
            for (int c = 0; c < 8; c++) wr[c] = Ws[kk * 257 + lane + c * 32];
#pragma unroll
            for (int r = 0; r < 8; r++)
#pragma unroll
                for (int c = 0; c < 8; c++)
                    acc[r][c] = fmaf(xr[r], wr[c], acc[r][c]);
        }
        __syncthreads();
    }

    float sc[8], mv[8], bb[8];
#pragma unroll
    for (int c = 0; c < 8; c++) {
        int col = lane + c * 32;
        sc[c] = bng[col] * rsqrtf(bnv[col] + LN_EPS);
        mv[c] = bnm[col];
        bb[c] = bnb[col];
    }
#pragma unroll
    for (int r = 0; r < 8; r++) {
        int hw = hw0 + wy * 8 + r;
        size_t tok = (size_t)b * NTOK + lvl_off + hw;
#pragma unroll
        for (int c = 0; c < 8; c++)
            Y[tok * 256 + lane + c * 32] = (acc[r][c] - mv[c]) * sc[c] + bb[c];
    }
}

// ---------------- loc final: [N,256] @ [256,1] + b ----------------
__global__ __launch_bounds__(256) void loc_final_kernel(
    const float* __restrict__ X, const float* __restrict__ Wf,
    const float* __restrict__ bf, float* __restrict__ out, int n)
{
    int t = blockIdx.x * 8 + (threadIdx.x >> 5);
    int lane = threadIdx.x & 31;
    if (t >= n) return;
    float s = 0.f;
#pragma unroll
    for (int j = 0; j < 8; j++)
        s = fmaf(X[(size_t)t * 256 + lane + j * 32], Wf[lane + j * 32], s);
#pragma unroll
    for (int o = 16; o > 0; o >>= 1) s += __shfl_xor_sync(0xffffffffu, s, o);
    if (lane == 0) out[t] = s + bf[0];
}

// ---------------- top-k (100, sorted desc, ties -> lowest index) ----------
__global__ __launch_bounds__(512) void topk_kernel(
    const float* __restrict__ logits, float* __restrict__ vals, int* __restrict__ idxs)
{
    __shared__ float sv[NTOK];
    __shared__ float rv[16];
    __shared__ int   ri[16];
    const int b = blockIdx.x, tid = threadIdx.x;
    for (int i = tid; i < NTOK; i += 512) sv[i] = logits[b * NTOK + i];
    __syncthreads();
    for (int k = 0; k < KINST; k++) {
        float bv = -3.0e38f; int bi = 0;
        for (int i = tid; i < NTOK; i += 512) {
            float v = sv[i];
            if (v > bv) { bv = v; bi = i; }     // ascending i -> lowest idx on tie
        }
#pragma unroll
        for (int o = 16; o > 0; o >>= 1) {
            float ov = __shfl_xor_sync(0xffffffffu, bv, o);
            int   oi = __shfl_xor_sync(0xffffffffu, bi, o);
            if (ov > bv || (ov == bv && oi < bi)) { bv = ov; bi = oi; }
        }
        if ((tid & 31) == 0) { rv[tid >> 5] = bv; ri[tid >> 5] = bi; }
        __syncthreads();
        if (tid == 0) {
            for (int w = 1; w < 16; w++)
                if (rv[w] > bv || (rv[w] == bv && ri[w] < bi)) { bv = rv[w]; bi = ri[w]; }
            vals[b * KINST + k] = bv;
            idxs[b * KINST + k] = bi;
            sv[bi] = -3.3e38f;
        }
        __syncthreads();
    }
}

// ---------------- gather top-k features ----------------
__global__ __launch_bounds__(64) void gather_kernel(
    const float* __restrict__ flat, const int* __restrict__ idxs, float* __restrict__ g)
{
    int i = blockIdx.x;
    int b = i / KINST;
    int n = idxs[i];
    const float4* src = (const float4*)(flat + ((size_t)b * NTOK + n) * 256);
    float4*       dst = (float4*)(g + (size_t)i * 256);
    dst[threadIdx.x] = src[threadIdx.x];
}

// ---------------- cls final: dot(256x80) + argmax ----------------
__global__ __launch_bounds__(128) void cls_final_kernel(
    const float* __restrict__ X, const float* __restrict__ Wf,
    const float* __restrict__ bf, float* __restrict__ out)
{
    __shared__ float xs[256];
    __shared__ float sval[80];
    int i = blockIdx.x, tid = threadIdx.x;
    if (tid < 64) ((float4*)xs)[tid] = ((const float4*)(X + (size_t)i * 256))[tid];
    __syncthreads();
    if (tid < 80) {
        float s = bf[tid];
        for (int k = 0; k < 256; k++) s = fmaf(xs[k], Wf[k * 80 + tid], s);
        sval[tid] = s;
    }
    __syncthreads();
    if (tid == 0) {
        float bv = sval[0]; int bi = 0;
        for (int t = 1; t < 80; t++) if (sval[t] > bv) { bv = sval[t]; bi = t; }
        out[CL_OFF + i] = (float)bi;
    }
}

__device__ __forceinline__ float read_dim(const int* p) {
    int v = p[0];
    if (v > 0 && v < 1000000) return (float)v;   // stored as int32
    return __int_as_float(v);                    // stored as float32
}

// ---------------- box final: dot(256x4) + exp + anchor decode ----------------
__global__ __launch_bounds__(128) void box_final_kernel(
    const float* __restrict__ X, const float* __restrict__ Wf,
    const float* __restrict__ bf, const int* __restrict__ idxs,
    const int* __restrict__ p_fh, const int* __restrict__ p_fw,
    float* __restrict__ out)
{
    __shared__ float xs[256];
    __shared__ float e[4];
    int i = blockIdx.x, tid = threadIdx.x, lane = tid & 31, w = tid >> 5;
    if (tid < 64) ((float4*)xs)[tid] = ((const float4*)(X + (size_t)i * 256))[tid];
    __syncthreads();
    float s = 0.f;
#pragma unroll
    for (int j = 0; j < 8; j++) {
        int k = lane + j * 32;
        s = fmaf(xs[k], Wf[k * 4 + w], s);
    }
#pragma unroll
    for (int o = 16; o > 0; o >>= 1) s += __shfl_xor_sync(0xffffffffu, s, o);
    if (lane == 0) e[w] = expf(s + bf[w]);
    __syncthreads();
    if (tid == 0) {
        int n = idxs[i];
        int hsz, m;
        if (n < 4096)      { hsz = 64; m = n; }
        else if (n < 5120) { hsz = 32; m = n - 4096; }
        else               { hsz = 16; m = n - 5120; }
        int gy = m / hsz, gx = m % hsz;
        float inv = 1.0f / (float)hsz;
        float ox = (gx + 0.5f) * inv, oy = (gy + 0.5f) * inv;
        float half = 0.5f * inv;
        float fw = read_dim(p_fw), fh = read_dim(p_fh);
        float* o4 = out + BX_OFF + (size_t)i * 4;
        o4[0] = (ox - half * e[0]) * fw;
        o4[1] = (oy - half * e[1]) * fh;
        o4[2] = (ox + half * e[2]) * fw;
        o4[3] = (oy + half * e[3]) * fh;
    }
}

// ---------------- scores + num_instances ----------------
__global__ __launch_bounds__(800) void scores_kernel(
    const float* __restrict__ vals, float* __restrict__ out)
{
    __shared__ int cnt[BATCH];
    int tid = threadIdx.x;
    if (tid < BATCH) cnt[tid] = 0;
    __syncthreads();
    float v = vals[tid];
    out[SC_OFF + tid] = 1.f / (1.f + expf(-v));
    if (v > 0.f) atomicAdd(&cnt[tid / KINST], 1);
    __syncthreads();
    if (tid < BATCH) out[NI_OFF + tid] = (float)cnt[tid];
}

// ---------------- host launcher ----------------
extern "C" void kernel_launch(void* const* d_in, const int* in_sizes, int n_in,
                              void* d_out, int out_size)
{
    const float* x3     = (const float*)d_in[0];
    const float* x4     = (const float*)d_in[1];
    const float* x5     = (const float*)d_in[2];
    const float* lat_w3 = (const float*)d_in[3];
    const float* lat_w4 = (const float*)d_in[4];
    const float* lat_w5 = (const float*)d_in[5];
    const float* bn_g   = (const float*)d_in[6];
    const float* bn_b   = (const float*)d_in[7];
    const float* bn_m   = (const float*)d_in[8];
    const float* bn_v   = (const float*)d_in[9];
    const float* loc_Ws = (const float*)d_in[10];
    const float* loc_bs = (const float*)d_in[11];
    const float* loc_lng= (const float*)d_in[12];
    const float* loc_lnb= (const float*)d_in[13];
    const float* loc_Wf = (const float*)d_in[14];
    const float* loc_bf = (const float*)d_in[15];
    const float* cls_Ws = (const float*)d_in[16];
    const float* cls_bs = (const float*)d_in[17];
    const float* cls_lng= (const float*)d_in[18];
    const float* cls_lnb= (const float*)d_in[19];
    const float* cls_Wf = (const float*)d_in[20];
    const float* cls_bf = (const float*)d_in[21];
    const float* box_Ws = (const float*)d_in[22];
    const float* box_bs = (const float*)d_in[23];
    const float* box_lng= (const float*)d_in[24];
    const float* box_lnb= (const float*)d_in[25];
    const float* box_Wf = (const float*)d_in[26];
    const float* box_bf = (const float*)d_in[27];
    const int*   p_fh   = (const int*)d_in[28];
    const int*   p_fw   = (const int*)d_in[29];
    float* out = (float*)d_out;

    float *flat, *h0, *h1, *logits, *vals, *gath; int* idxp;
    cudaGetSymbolAddress((void**)&flat,   g_flat);
    cudaGetSymbolAddress((void**)&h0,     g_h0);
    cudaGetSymbolAddress((void**)&h1,     g_h1);
    cudaGetSymbolAddress((void**)&logits, g_logits);
    cudaGetSymbolAddress((void**)&vals,   g_vals);
    cudaGetSymbolAddress((void**)&idxp,   g_idx);
    cudaGetSymbolAddress((void**)&gath,   g_gath);

    // 1) laterals -> g_flat
    lateral_kernel<<<8*4096/64, 256>>>(x3, lat_w3, 256, 4096,
        bn_g + 0*C, bn_b + 0*C, bn_m + 0*C, bn_v + 0*C, 0, flat);
    lateral_kernel<<<8*1024/64, 256>>>(x4, lat_w4, 512, 1024,
        bn_g + 1*C, bn_b + 1*C, bn_m + 1*C, bn_v + 1*C, 4096, flat);
    lateral_kernel<<<8*256/64, 256>>>(x5, lat_w5, 1024, 256,
        bn_g + 2*C, bn_b + 2*C, bn_m + 2*C, bn_v + 2*C, 5120, flat);

    // 2) loc MLP (4 fused layers), ping-pong
    {
        const float* cur = flat;
        float* bufs[2] = { h0, h1 };
        for (int i = 0; i < 4; i++) {
            float* dst = bufs[i & 1];
            gemm_mlp_ln_silu<<<TOT/64, 256>>>(cur,
                loc_Ws + (size_t)i*C*C, loc_bs + i*C,
                loc_lng + i*C, loc_lnb + i*C, dst, TOT);
            cur = dst;
        }
        loc_final_kernel<<<TOT/8, 256>>>(cur, loc_Wf, loc_bf, logits, TOT);
    }

    // 3) top-k + gather
    topk_kernel<<<BATCH, 512>>>(logits, vals, idxp);
    gather_kernel<<<BATCH*KINST, 64>>>(flat, idxp, gath);

    const int HROWS = BATCH * KINST;          // 800
    const int HBLK  = (HROWS + 63) / 64;      // 13

    // 4) cls head
    {
        const float* cur = gath;
        float* bufs[2] = { h0, h1 };
        for (int i = 0; i < 4; i++) {
            float* dst = bufs[i & 1];
            gemm_mlp_ln_silu<<<HBLK, 256>>>(cur,
                cls_Ws + (size_t)i*C*C, cls_bs + i*C,
                cls_lng + i*C, cls_lnb + i*C, dst, HROWS);
            cur = dst;
        }
        cls_final_kernel<<<HROWS, 128>>>(cur, cls_Wf, cls_bf, out);
    }

    // 5) box head
    {
        const float* cur = gath;
        float* bufs[2] = { h0, h1 };
        for (int i = 0; i < 4; i++) {
            float* dst = bufs[i & 1];
            gemm_mlp_ln_silu<<<HBLK, 256>>>(cur,
                box_Ws + (size_t)i*C*C, box_bs + i*C,
                box_lng + i*C, box_lnb + i*C, dst, HROWS);
            cur = dst;
        }
        box_final_kernel<<<HROWS, 128>>>(cur, box_Wf, box_bf, idxp, p_fh, p_fw, out);
    }

    // 6) scores + num_instances
    scores_kernel<<<1, 800>>>(vals, out);
}

// round 3
// speedup vs baseline: 1.3234x; 1.3234x over previous
#include <cuda_runtime.h>
#include <cuda_bf16.h>
#include <math.h>
#include <stdint.h>

#define C 256
#define BATCH 8
#define NTOK 5376
#define TOT (BATCH*NTOK)   /* 43008 */
#define KINST 100
#define LN_EPS 1e-5f

#define NI_OFF 0
#define SC_OFF 8
#define CL_OFF 808
#define BX_OFF 1608

// ---------------- device scratch ----------------
__device__ float g_flat[TOT*C];
__device__ float g_h0[TOT*C];
__device__ float g_h1[TOT*C];
__device__ float g_logits[TOT];
__device__ float g_vals[BATCH*KINST];
__device__ int   g_idx[BATCH*KINST];
__device__ float g_gath[BATCH*KINST*C];
__device__ __nv_bfloat16 g_whi[12*65536];
__device__ __nv_bfloat16 g_wlo[12*65536];
__device__ __nv_bfloat16 g_lathi[458752];
__device__ __nv_bfloat16 g_latlo[458752];

// ---------------- helpers ----------------
__device__ __forceinline__ uint32_t smem_u32(const void* p){
    uint32_t a;
    asm("{ .reg .u64 t; cvta.to.shared.u64 t, %1; cvt.u32.u64 %0, t; }" : "=r"(a) : "l"(p));
    return a;
}
__device__ __forceinline__ uint32_t sw128(uint32_t o){ return o ^ ((o >> 3) & 0x70); }

__device__ __forceinline__ void ldsm4(uint32_t addr, uint32_t& r0, uint32_t& r1,
                                      uint32_t& r2, uint32_t& r3){
    asm volatile("ldmatrix.sync.aligned.m8n8.x4.shared.b16 {%0,%1,%2,%3}, [%4];"
                 : "=r"(r0), "=r"(r1), "=r"(r2), "=r"(r3) : "r"(addr));
}
__device__ __forceinline__ void mma_bf16(float* d, const uint32_t* a, uint32_t b0, uint32_t b1){
    asm volatile(
        "mma.sync.aligned.m16n8k16.row.col.f32.bf16.bf16.f32 "
        "{%0,%1,%2,%3}, {%4,%5,%6,%7}, {%8,%9}, {%0,%1,%2,%3};"
        : "+f"(d[0]), "+f"(d[1]), "+f"(d[2]), "+f"(d[3])
        : "r"(a[0]), "r"(a[1]), "r"(a[2]), "r"(a[3]), "r"(b0), "r"(b1));
}

__device__ __forceinline__ void hl4(const float4 v, uint2& h, uint2& l){
    __nv_bfloat16 h0=__float2bfloat16(v.x), h1=__float2bfloat16(v.y),
                  h2=__float2bfloat16(v.z), h3=__float2bfloat16(v.w);
    float r0=v.x-__bfloat162float(h0), r1=v.y-__bfloat162float(h1),
          r2=v.z-__bfloat162float(h2), r3=v.w-__bfloat162float(h3);
    h.x = (uint32_t)__bfloat16_as_ushort(h0) | ((uint32_t)__bfloat16_as_ushort(h1)<<16);
    h.y = (uint32_t)__bfloat16_as_ushort(h2) | ((uint32_t)__bfloat16_as_ushort(h3)<<16);
    __nv_bfloat16 l0=__float2bfloat16(r0), l1=__float2bfloat16(r1),
                  l2=__float2bfloat16(r2), l3=__float2bfloat16(r3);
    l.x = (uint32_t)__bfloat16_as_ushort(l0) | ((uint32_t)__bfloat16_as_ushort(l1)<<16);
    l.y = (uint32_t)__bfloat16_as_ushort(l2) | ((uint32_t)__bfloat16_as_ushort(l3)<<16);
}

// ---------------- smem layout (bytes) ----------------
#define AH_OFF 0
#define AL_OFF 16384
#define BH_OFF 32768
#define BL_OFF 65536
#define PB_OFF 98304    /* bias 256 f */
#define PG_OFF 99328    /* gamma */
#define PO_OFF 100352   /* beta  */
#define RS_OFF 101376   /* rowsum 128 f */
#define RQ_OFF 101888   /* rowsq 128 f */
#define SMEM_TOTAL 102400

// ============================================================================
// tc_gemm: D[128-row tile, 256] = X @ W via bf16x3-compensated mma.sync.
// mode 0: +bias -> LayerNorm -> SiLU.  mode 1: lateral conv + BN affine.
// ============================================================================
__global__ __launch_bounds__(256) void tc_gemm(
    const float* __restrict__ X, const __nv_bfloat16* __restrict__ Whi,
    const __nv_bfloat16* __restrict__ Wlo, int Kdim, int mode, int HW, int lvl_off,
    const float* __restrict__ p_bias, const float* __restrict__ p_g,
    const float* __restrict__ p_b, const float* __restrict__ p_m,
    const float* __restrict__ p_v, float* __restrict__ Y, int nrows)
{
    extern __shared__ char smem[];
    const uint32_t sbase = smem_u32(smem);
    const int tid  = threadIdx.x;
    const int lane = tid & 31;
    const int wid  = tid >> 5;
    const int wm   = wid >> 2;       // 0..1 (64-row half)
    const int wn   = wid & 3;        // 0..3 (64-col slice)
    const int row0 = blockIdx.x * 128;

    // params -> smem
    if (mode == 0) {
        ((float*)(smem+PB_OFF))[tid] = p_bias[tid];
        ((float*)(smem+PG_OFF))[tid] = p_g[tid];
        ((float*)(smem+PO_OFF))[tid] = p_b[tid];
    } else {
        float sc = p_g[tid] * rsqrtf(p_v[tid] + LN_EPS);
        ((float*)(smem+PG_OFF))[tid] = sc;
        ((float*)(smem+PO_OFF))[tid] = p_b[tid] - p_m[tid] * sc;
    }
    if (tid < 128) {
        ((float*)(smem+RS_OFF))[tid] = 0.f;
        ((float*)(smem+RQ_OFF))[tid] = 0.f;
    }

    int bb_lat = 0, hw0 = 0;
    if (mode == 1) { bb_lat = row0 / HW; hw0 = row0 % HW; }

    float acc[4][8][4];
#pragma unroll
    for (int mi = 0; mi < 4; mi++)
#pragma unroll
        for (int ni = 0; ni < 8; ni++)
#pragma unroll
            for (int q = 0; q < 4; q++) acc[mi][ni][q] = 0.f;

    // ldmatrix lane -> (row-offset, kByte-offset) inside a 16x16 tile
    const int lm_r = (lane & 7) + ((lane >> 3) & 1) * 8;
    const int lm_k = (lane >> 4) * 16;

    const int nch = Kdim >> 6;
    for (int kc = 0; kc < nch; kc++) {
        const int k0 = kc * 64;
        // ---- A tile: 128 rows x 64 k, bf16 hi/lo, SW128 rows of 128B ----
        if (mode == 0) {
#pragma unroll
            for (int j = 0; j < 8; j++) {
                int f = tid + j * 256;
                int r = f >> 4, k4 = (f & 15) * 4;
                int rg = row0 + r; if (rg >= nrows) rg = nrows - 1;
                float4 v = *(const float4*)(X + (size_t)rg * Kdim + k0 + k4);
                uint2 h, l; hl4(v, h, l);
                uint32_t so = sw128((uint32_t)(r * 128 + k4 * 2));
                *(uint2*)(smem + AH_OFF + so) = h;
                *(uint2*)(smem + AL_OFF + so) = l;
            }
        } else {
#pragma unroll
            for (int j = 0; j < 8; j++) {
                int f = tid + j * 256;
                int kk = f >> 5, r4 = (f & 31) * 4;
                float4 v = *(const float4*)(X + ((size_t)(bb_lat * Kdim + k0 + kk)) * HW + hw0 + r4);
                float xs[4] = { v.x, v.y, v.z, v.w };
#pragma unroll
                for (int t = 0; t < 4; t++) {
                    __nv_bfloat16 h = __float2bfloat16(xs[t]);
                    __nv_bfloat16 l = __float2bfloat16(xs[t] - __bfloat162float(h));
                    uint32_t so = sw128((uint32_t)((r4 + t) * 128 + kk * 2));
                    *(unsigned short*)(smem + AH_OFF + so) = __bfloat16_as_ushort(h);
                    *(unsigned short*)(smem + AL_OFF + so) = __bfloat16_as_ushort(l);
                }
            }
        }
        // ---- B tile: 256 o-rows x 64 k ----
#pragma unroll
        for (int j = 0; j < 16; j++) {
            int f = tid + j * 256;
            int o = f >> 4, kg = (f & 15) * 4;
            size_t gi = (size_t)o * Kdim + k0 + kg;
            uint2 h = *(const uint2*)(Whi + gi);
            uint2 l = *(const uint2*)(Wlo + gi);
            uint32_t so = sw128((uint32_t)(o * 128 + kg * 2));
            *(uint2*)(smem + BH_OFF + so) = h;
            *(uint2*)(smem + BL_OFF + so) = l;
        }
        __syncthreads();

        // ---- compute: 4 ksteps of 16 ----
#pragma unroll
        for (int ks = 0; ks < 4; ks++) {
            const int kb = ks * 32 + lm_k;
            uint32_t ah[4][4], al[4][4];
#pragma unroll
            for (int mi = 0; mi < 4; mi++) {
                int row = wm * 64 + mi * 16 + lm_r;
                uint32_t so = sw128((uint32_t)(row * 128 + kb));
                ldsm4(sbase + AH_OFF + so, ah[mi][0], ah[mi][1], ah[mi][2], ah[mi][3]);
                ldsm4(sbase + AL_OFF + so, al[mi][0], al[mi][1], al[mi][2], al[mi][3]);
            }
#pragma unroll
            for (int bi = 0; bi < 4; bi++) {
                int nr = wn * 64 + bi * 16 + lm_r;
                uint32_t so = sw128((uint32_t)(nr * 128 + kb));
                uint32_t bh0, bh1, bh2, bh3, bl0, bl1, bl2, bl3;
                ldsm4(sbase + BH_OFF + so, bh0, bh1, bh2, bh3);
                ldsm4(sbase + BL_OFF + so, bl0, bl1, bl2, bl3);
#pragma unroll
                for (int mi = 0; mi < 4; mi++) {
                    mma_bf16(acc[mi][2*bi],   ah[mi], bh0, bh2);
                    mma_bf16(acc[mi][2*bi+1], ah[mi], bh1, bh3);
                    mma_bf16(acc[mi][2*bi],   ah[mi], bl0, bl2);
                    mma_bf16(acc[mi][2*bi+1], ah[mi], bl1, bl3);
                    mma_bf16(acc[mi][2*bi],   al[mi], bh0, bh2);
                    mma_bf16(acc[mi][2*bi+1], al[mi], bh1, bh3);
                }
            }
        }
        __syncthreads();
    }

    // ---- epilogue ----
    const float* f_bias = (float*)(smem + PB_OFF);
    const float* f_g    = (float*)(smem + PG_OFF);
    const float* f_o    = (float*)(smem + PO_OFF);
    float* rowsum = (float*)(smem + RS_OFF);
    float* rowsq  = (float*)(smem + RQ_OFF);
    const int rloc = (lane >> 2);               // 0..7 within 16-row tile

    if (mode == 0) {
        // bias add + row stats
#pragma unroll
        for (int mi = 0; mi < 4; mi++) {
            float sA = 0.f, qA = 0.f, sB = 0.f, qB = 0.f;
#pragma unroll
            for (int ni = 0; ni < 8; ni++) {
                int c0 = wn * 64 + ni * 8 + (lane & 3) * 2;
                float b0 = f_bias[c0], b1 = f_bias[c0+1];
                float v0 = acc[mi][ni][0] + b0;
                float v1 = acc[mi][ni][1] + b1;
                float v2 = acc[mi][ni][2] + b0;
                float v3 = acc[mi][ni][3] + b1;
                acc[mi][ni][0]=v0; acc[mi][ni][1]=v1; acc[mi][ni][2]=v2; acc[mi][ni][3]=v3;
                sA += v0 + v1; qA += v0*v0 + v1*v1;
                sB += v2 + v3; qB += v2*v2 + v3*v3;
            }
#pragma unroll
            for (int o = 1; o <= 2; o <<= 1) {
                sA += __shfl_xor_sync(0xffffffffu, sA, o);
                qA += __shfl_xor_sync(0xffffffffu, qA, o);
                sB += __shfl_xor_sync(0xffffffffu, sB, o);
                qB += __shfl_xor_sync(0xffffffffu, qB, o);
            }
            if ((lane & 3) == 0) {
                int rA = wm * 64 + mi * 16 + rloc;
                atomicAdd(&rowsum[rA], sA);   atomicAdd(&rowsq[rA], qA);
                atomicAdd(&rowsum[rA+8], sB); atomicAdd(&rowsq[rA+8], qB);
            }
        }
        __syncthreads();
#pragma unroll
        for (int mi = 0; mi < 4; mi++) {
            int rA = wm * 64 + mi * 16 + rloc;
            int rB = rA + 8;
            float mA = rowsum[rA] * (1.f/256.f);
            float rsA = rsqrtf(rowsq[rA] * (1.f/256.f) - mA*mA + LN_EPS);
            float mB = rowsum[rB] * (1.f/256.f);
            float rsB = rsqrtf(rowsq[rB] * (1.f/256.f) - mB*mB + LN_EPS);
            int rgA = row0 + rA, rgB = row0 + rB;
#pragma unroll
            for (int ni = 0; ni < 8; ni++) {
                int c0 = wn * 64 + ni * 8 + (lane & 3) * 2;
                float g0 = f_g[c0], g1 = f_g[c0+1], o0 = f_o[c0], o1 = f_o[c0+1];
                float u0 = (acc[mi][ni][0] - mA) * rsA * g0 + o0;
                float u1 = (acc[mi][ni][1] - mA) * rsA * g1 + o1;
                float u2 = (acc[mi][ni][2] - mB) * rsB * g0 + o0;
                float u3 = (acc[mi][ni][3] - mB) * rsB * g1 + o1;
                u0 = u0 / (1.f + expf(-u0));
                u1 = u1 / (1.f + expf(-u1));
                u2 = u2 / (1.f + expf(-u2));
                u3 = u3 / (1.f + expf(-u3));
                if (rgA < nrows) *(float2*)(Y + (size_t)rgA * 256 + c0) = make_float2(u0, u1);
                if (rgB < nrows) *(float2*)(Y + (size_t)rgB * 256 + c0) = make_float2(u2, u3);
            }
        }
    } else {
#pragma unroll
        for (int mi = 0; mi < 4; mi++) {
            int rA = wm * 64 + mi * 16 + rloc;
            int rB = rA + 8;
            size_t oA = (size_t)bb_lat * NTOK + lvl_off + hw0 + rA;
            size_t oB = (size_t)bb_lat * NTOK + lvl_off + hw0 + rB;
#pragma unroll
            for (int ni = 0; ni < 8; ni++) {
                int c0 = wn * 64 + ni * 8 + (lane & 3) * 2;
                float g0 = f_g[c0], g1 = f_g[c0+1], o0 = f_o[c0], o1 = f_o[c0+1];
                *(float2*)(Y + oA * 256 + c0) =
                    make_float2(acc[mi][ni][0]*g0+o0, acc[mi][ni][1]*g1+o1);
                *(float2*)(Y + oB * 256 + c0) =
                    make_float2(acc[mi][ni][2]*g0+o0, acc[mi][ni][3]*g1+o1);
            }
        }
    }
}

// ---------------- weight prep: head mats [K,O] -> bf16 hi/lo [O,K] ----------
__global__ __launch_bounds__(256) void prep_tr(
    const float* __restrict__ locw, const float* __restrict__ clsw,
    const float* __restrict__ boxw, __nv_bfloat16* __restrict__ hi,
    __nv_bfloat16* __restrict__ lo)
{
    int mat = blockIdx.x >> 8;
    int o   = blockIdx.x & 255;
    int k   = threadIdx.x;
    const float* W = (mat < 4 ? locw : (mat < 8 ? clsw : boxw)) + (size_t)(mat & 3) * 65536;
    float v = W[k * 256 + o];
    __nv_bfloat16 h = __float2bfloat16(v);
    size_t oi = (size_t)mat * 65536 + (size_t)o * 256 + k;
    hi[oi] = h;
    lo[oi] = __float2bfloat16(v - __bfloat162float(h));
}

__global__ __launch_bounds__(256) void prep_direct(
    const float* __restrict__ W, __nv_bfloat16* __restrict__ hi,
    __nv_bfloat16* __restrict__ lo, int n)
{
    int i = blockIdx.x * 256 + threadIdx.x;
    if (i < n) {
        float v = W[i];
        __nv_bfloat16 h = __float2bfloat16(v);
        hi[i] = h;
        lo[i] = __float2bfloat16(v - __bfloat162float(h));
    }
}

// ---------------- loc final: [N,256] @ [256,1] + b ----------------
__global__ __launch_bounds__(256) void loc_final_kernel(
    const float* __restrict__ X, const float* __restrict__ Wf,
    const float* __restrict__ bf, float* __restrict__ out, int n)
{
    int t = blockIdx.x * 8 + (threadIdx.x >> 5);
    int lane = threadIdx.x & 31;
    if (t >= n) return;
    float s = 0.f;
#pragma unroll
    for (int j = 0; j < 8; j++)
        s = fmaf(X[(size_t)t * 256 + lane + j * 32], Wf[lane + j * 32], s);
#pragma unroll
    for (int o = 16; o > 0; o >>= 1) s += __shfl_xor_sync(0xffffffffu, s, o);
    if (lane == 0) out[t] = s + bf[0];
}

// ---------------- top-k ----------------
__global__ __launch_bounds__(512) void topk_kernel(
    const float* __restrict__ logits, float* __restrict__ vals, int* __restrict__ idxs)
{
    __shared__ float sv[NTOK];
    __shared__ float rv[16];
    __shared__ int   ri[16];
    const int b = blockIdx.x, tid = threadIdx.x;
    for (int i = tid; i < NTOK; i += 512) sv[i] = logits[b * NTOK + i];
    __syncthreads();
    for (int k = 0; k < KINST; k++) {
        float bv = -3.0e38f; int bi = 0;
        for (int i = tid; i < NTOK; i += 512) {
            float v = sv[i];
            if (v > bv) { bv = v; bi = i; }
        }
#pragma unroll
        for (int o = 16; o > 0; o >>= 1) {
            float ov = __shfl_xor_sync(0xffffffffu, bv, o);
            int   oi = __shfl_xor_sync(0xffffffffu, bi, o);
            if (ov > bv || (ov == bv && oi < bi)) { bv = ov; bi = oi; }
        }
        if ((tid & 31) == 0) { rv[tid >> 5] = bv; ri[tid >> 5] = bi; }
        __syncthreads();
        if (tid == 0) {
            for (int w = 1; w < 16; w++)
                if (rv[w] > bv || (rv[w] == bv && ri[w] < bi)) { bv = rv[w]; bi = ri[w]; }
            vals[b * KINST + k] = bv;
            idxs[b * KINST + k] = bi;
            sv[bi] = -3.3e38f;
        }
        __syncthreads();
    }
}

// ---------------- gather ----------------
__global__ __launch_bounds__(64) void gather_kernel(
    const float* __restrict__ flat, const int* __restrict__ idxs, float* __restrict__ g)
{
    int i = blockIdx.x;
    int b = i / KINST;
    int n = idxs[i];
    const float4* src = (const float4*)(flat + ((size_t)b * NTOK + n) * 256);
    float4*       dst = (float4*)(g + (size_t)i * 256);
    dst[threadIdx.x] = src[threadIdx.x];
}

// ---------------- cls final ----------------
__global__ __launch_bounds__(128) void cls_final_kernel(
    const float* __restrict__ X, const float* __restrict__ Wf,
    const float* __restrict__ bf, float* __restrict__ out)
{
    __shared__ float xs[256];
    __shared__ float sval[80];
    int i = blockIdx.x, tid = threadIdx.x;
    if (tid < 64) ((float4*)xs)[tid] = ((const float4*)(X + (size_t)i * 256))[tid];
    __syncthreads();
    if (tid < 80) {
        float s = bf[tid];
        for (int k = 0; k < 256; k++) s = fmaf(xs[k], Wf[k * 80 + tid], s);
        sval[tid] = s;
    }
    __syncthreads();
    if (tid == 0) {
        float bv = sval[0]; int bi = 0;
        for (int t = 1; t < 80; t++) if (sval[t] > bv) { bv = sval[t]; bi = t; }
        out[CL_OFF + i] = (float)bi;
    }
}

__device__ __forceinline__ float read_dim(const int* p) {
    int v = p[0];
    if (v > 0 && v < 1000000) return (float)v;
    return __int_as_float(v);
}

// ---------------- box final ----------------
__global__ __launch_bounds__(128) void box_final_kernel(
    const float* __restrict__ X, const float* __restrict__ Wf,
    const float* __restrict__ bf, const int* __restrict__ idxs,
    const int* __restrict__ p_fh, const int* __restrict__ p_fw,
    float* __restrict__ out)
{
    __shared__ float xs[256];
    __shared__ float e[4];
    int i = blockIdx.x, tid = threadIdx.x, lane = tid & 31, w = tid >> 5;
    if (tid < 64) ((float4*)xs)[tid] = ((const float4*)(X + (size_t)i * 256))[tid];
    __syncthreads();
    float s = 0.f;
#pragma unroll
    for (int j = 0; j < 8; j++) {
        int k = lane + j * 32;
        s = fmaf(xs[k], Wf[k * 4 + w], s);
    }
#pragma unroll
    for (int o = 16; o > 0; o >>= 1) s += __shfl_xor_sync(0xffffffffu, s, o);
    if (lane == 0) e[w] = expf(s + bf[w]);
    __syncthreads();
    if (tid == 0) {
        int n = idxs[i];
        int hsz, m;
        if (n < 4096)      { hsz = 64; m = n; }
        else if (n < 5120) { hsz = 32; m = n - 4096; }
        else               { hsz = 16; m = n - 5120; }
        int gy = m / hsz, gx = m % hsz;
        float inv = 1.0f / (float)hsz;
        float ox = (gx + 0.5f) * inv, oy = (gy + 0.5f) * inv;
        float half = 0.5f * inv;
        float fw = read_dim(p_fw), fh = read_dim(p_fh);
        float* o4 = out + BX_OFF + (size_t)i * 4;
        o4[0] = (ox - half * e[0]) * fw;
        o4[1] = (oy - half * e[1]) * fh;
        o4[2] = (ox + half * e[2]) * fw;
        o4[3] = (oy + half * e[3]) * fh;
    }
}

// ---------------- scores + num_instances ----------------
__global__ __launch_bounds__(800) void scores_kernel(
    const float* __restrict__ vals, float* __restrict__ out)
{
    __shared__ int cnt[BATCH];
    int tid = threadIdx.x;
    if (tid < BATCH) cnt[tid] = 0;
    __syncthreads();
    float v = vals[tid];
    out[SC_OFF + tid] = 1.f / (1.f + expf(-v));
    if (v > 0.f) atomicAdd(&cnt[tid / KINST], 1);
    __syncthreads();
    if (tid < BATCH) out[NI_OFF + tid] = (float)cnt[tid];
}

// ---------------- host launcher ----------------
extern "C" void kernel_launch(void* const* d_in, const int* in_sizes, int n_in,
                              void* d_out, int out_size)
{
    const float* x3     = (const float*)d_in[0];
    const float* x4     = (const float*)d_in[1];
    const float* x5     = (const float*)d_in[2];
    const float* lat_w3 = (const float*)d_in[3];
    const float* lat_w4 = (const float*)d_in[4];
    const float* lat_w5 = (const float*)d_in[5];
    const float* bn_g   = (const float*)d_in[6];
    const float* bn_b   = (const float*)d_in[7];
    const float* bn_m   = (const float*)d_in[8];
    const float* bn_v   = (const float*)d_in[9];
    const float* loc_Ws = (const float*)d_in[10];
    const float* loc_bs = (const float*)d_in[11];
    const float* loc_lng= (const float*)d_in[12];
    const float* loc_lnb= (const float*)d_in[13];
    const float* loc_Wf = (const float*)d_in[14];
    const float* loc_bf = (const float*)d_in[15];
    const float* cls_Ws = (const float*)d_in[16];
    const float* cls_bs = (const float*)d_in[17];
    const float* cls_lng= (const float*)d_in[18];
    const float* cls_lnb= (const float*)d_in[19];
    const float* cls_Wf = (const float*)d_in[20];
    const float* cls_bf = (const float*)d_in[21];
    const float* box_Ws = (const float*)d_in[22];
    const float* box_bs = (const float*)d_in[23];
    const float* box_lng= (const float*)d_in[24];
    const float* box_lnb= (const float*)d_in[25];
    const float* box_Wf = (const float*)d_in[26];
    const float* box_bf = (const float*)d_in[27];
    const int*   p_fh   = (const int*)d_in[28];
    const int*   p_fw   = (const int*)d_in[29];
    float* out = (float*)d_out;

    float *flat, *h0, *h1, *logits, *vals, *gath; int* idxp;
    __nv_bfloat16 *whi, *wlo, *lathi, *latlo;
    cudaGetSymbolAddress((void**)&flat,   g_flat);
    cudaGetSymbolAddress((void**)&h0,     g_h0);
    cudaGetSymbolAddress((void**)&h1,     g_h1);
    cudaGetSymbolAddress((void**)&logits, g_logits);
    cudaGetSymbolAddress((void**)&vals,   g_vals);
    cudaGetSymbolAddress((void**)&idxp,   g_idx);
    cudaGetSymbolAddress((void**)&gath,   g_gath);
    cudaGetSymbolAddress((void**)&whi,    g_whi);
    cudaGetSymbolAddress((void**)&wlo,    g_wlo);
    cudaGetSymbolAddress((void**)&lathi,  g_lathi);
    cudaGetSymbolAddress((void**)&latlo,  g_latlo);

    cudaFuncSetAttribute(tc_gemm, cudaFuncAttributeMaxDynamicSharedMemorySize, SMEM_TOTAL);

    // 0) weight prep
    prep_tr<<<12*256, 256>>>(loc_Ws, cls_Ws, box_Ws, whi, wlo);
    prep_direct<<<(65536+255)/256, 256>>>(lat_w3, lathi, latlo, 65536);
    prep_direct<<<(131072+255)/256, 256>>>(lat_w4, lathi + 65536, latlo + 65536, 131072);
    prep_direct<<<(262144+255)/256, 256>>>(lat_w5, lathi + 196608, latlo + 196608, 262144);

    // 1) laterals -> g_flat
    tc_gemm<<<BATCH*4096/128, 256, SMEM_TOTAL>>>(x3, lathi,          latlo,          256,  1, 4096, 0,
        bn_b, bn_g + 0*C, bn_b + 0*C, bn_m + 0*C, bn_v + 0*C, flat, BATCH*4096);
    tc_gemm<<<BATCH*1024/128, 256, SMEM_TOTAL>>>(x4, lathi + 65536,  latlo + 65536,  512,  1, 1024, 4096,
        bn_b, bn_g + 1*C, bn_b + 1*C, bn_m + 1*C, bn_v + 1*C, flat, BATCH*1024);
    tc_gemm<<<BATCH*256/128, 256, SMEM_TOTAL>>>(x5, lathi + 196608, latlo + 196608, 1024, 1, 256, 5120,
        bn_b, bn_g + 2*C, bn_b + 2*C, bn_m + 2*C, bn_v + 2*C, flat, BATCH*256);

    // 2) loc MLP
    {
        const float* cur = flat;
        float* bufs[2] = { h0, h1 };
        for (int i = 0; i < 4; i++) {
            float* dst = bufs[i & 1];
            tc_gemm<<<TOT/128, 256, SMEM_TOTAL>>>(cur, whi + (size_t)i*65536, wlo + (size_t)i*65536,
                256, 0, 0, 0, loc_bs + i*C, loc_lng + i*C, loc_lnb + i*C, 0, 0, dst, TOT);
            cur = dst;
        }
        loc_final_kernel<<<TOT/8, 256>>>(cur, loc_Wf, loc_bf, logits, TOT);
    }

    // 3) top-k + gather
    topk_kernel<<<BATCH, 512>>>(logits, vals, idxp);
    gather_kernel<<<BATCH*KINST, 64>>>(flat, idxp, gath);

    const int HROWS = BATCH * KINST;            // 800
    const int HBLK  = (HROWS + 127) / 128;      // 7

    // 4) cls head
    {
        const float* cur = gath;
        float* bufs[2] = { h0, h1 };
        for (int i = 0; i < 4; i++) {
            float* dst = bufs[i & 1];
            tc_gemm<<<HBLK, 256, SMEM_TOTAL>>>(cur, whi + (size_t)(4+i)*65536, wlo + (size_t)(4+i)*65536,
                256, 0, 0, 0, cls_bs + i*C, cls_lng + i*C, cls_lnb + i*C, 0, 0, dst, HROWS);
            cur = dst;
        }
        cls_final_kernel<<<HROWS, 128>>>(cur, cls_Wf, cls_bf, out);
    }

    // 5) box head
    {
        const float* cur = gath;
        float* bufs[2] = { h0, h1 };
        for (int i = 0; i < 4; i++) {
            float* dst = bufs[i & 1];
            tc_gemm<<<HBLK, 256, SMEM_TOTAL>>>(cur, whi + (size_t)(8+i)*65536, wlo + (size_t)(8+i)*65536,
                256, 0, 0, 0, box_bs + i*C, box_lng + i*C, box_lnb + i*C, 0, 0, dst, HROWS);
            cur = dst;
        }
        box_final_kernel<<<HROWS, 128>>>(cur, box_Wf, box_bf, idxp, p_fh, p_fw, out);
    }

    // 6) scores + num_instances
    scores_kernel<<<1, 800>>>(vals, out);
}

// round 4
// speedup vs baseline: 1.5073x; 1.1390x over previous
#include <cuda_runtime.h>
#include <cuda_bf16.h>
#include <math.h>
#include <stdint.h>

#define C 256
#define BATCH 8
#define NTOK 5376
#define TOT (BATCH*NTOK)   /* 43008 */
#define KINST 100
#define LN_EPS 1e-5f

#define NI_OFF 0
#define SC_OFF 8
#define CL_OFF 808
#define BX_OFF 1608

// ---------------- device scratch ----------------
__device__ __nv_bfloat16 g_flathi[TOT*C], g_flatlo[TOT*C];
__device__ __nv_bfloat16 g_p0hi[TOT*C],  g_p0lo[TOT*C];
__device__ __nv_bfloat16 g_p1hi[TOT*C],  g_p1lo[TOT*C];
__device__ float g_logits[TOT];
__device__ float g_vals[BATCH*KINST];
__device__ int   g_idx[BATCH*KINST];
__device__ __nv_bfloat16 g_hd[8][896*256];   // head ping-pong planes
__device__ __nv_bfloat16 g_whi[12*65536];
__device__ __nv_bfloat16 g_wlo[12*65536];
__device__ __nv_bfloat16 g_lathi[458752];
__device__ __nv_bfloat16 g_latlo[458752];

// ---------------- helpers ----------------
__device__ __forceinline__ uint32_t smem_u32(const void* p){
    uint32_t a;
    asm("{ .reg .u64 t; cvta.to.shared.u64 t, %1; cvt.u32.u64 %0, t; }" : "=r"(a) : "l"(p));
    return a;
}
__device__ __forceinline__ uint32_t sw128(uint32_t o){ return o ^ ((o >> 3) & 0x70); }

__device__ __forceinline__ void ldsm4(uint32_t addr, uint32_t& r0, uint32_t& r1,
                                      uint32_t& r2, uint32_t& r3){
    asm volatile("ldmatrix.sync.aligned.m8n8.x4.shared.b16 {%0,%1,%2,%3}, [%4];"
                 : "=r"(r0), "=r"(r1), "=r"(r2), "=r"(r3) : "r"(addr));
}
__device__ __forceinline__ void mma_bf16(float* d, const uint32_t* a, uint32_t b0, uint32_t b1){
    asm volatile(
        "mma.sync.aligned.m16n8k16.row.col.f32.bf16.bf16.f32 "
        "{%0,%1,%2,%3}, {%4,%5,%6,%7}, {%8,%9}, {%0,%1,%2,%3};"
        : "+f"(d[0]), "+f"(d[1]), "+f"(d[2]), "+f"(d[3])
        : "r"(a[0]), "r"(a[1]), "r"(a[2]), "r"(a[3]), "r"(b0), "r"(b1));
}
__device__ __forceinline__ void cpasync16(uint32_t dst, const void* src){
    asm volatile("cp.async.cg.shared.global [%0], [%1], 16;" :: "r"(dst), "l"(src));
}
__device__ __forceinline__ void cp_commit(){
    asm volatile("cp.async.commit_group;" ::: "memory");
}
__device__ __forceinline__ void store_hl2(__nv_bfloat16* Yhi, __nv_bfloat16* Ylo,
                                          size_t row, int c0, float u0, float u1){
    __nv_bfloat16 h0=__float2bfloat16(u0), h1=__float2bfloat16(u1);
    __nv_bfloat16 l0=__float2bfloat16(u0-__bfloat162float(h0));
    __nv_bfloat16 l1=__float2bfloat16(u1-__bfloat162float(h1));
    __nv_bfloat162 hh; hh.x=h0; hh.y=h1;
    __nv_bfloat162 ll; ll.x=l0; ll.y=l1;
    *(__nv_bfloat162*)(Yhi+row*256+c0) = hh;
    *(__nv_bfloat162*)(Ylo+row*256+c0) = ll;
}

// ---------------- smem layout (bytes) ----------------
#define STAGE   98304
#define AH_OFF  0
#define AL_OFF  16384
#define BH_OFF  32768
#define BL_OFF  65536
#define P_PB    196608
#define P_PG    197632
#define P_PO    198656
#define P_WF    199680
#define P_RS    200704
#define P_RQ    201216
#define P_RD    201728
#define P_SIDX  202240
#define SMEM_TOTAL 202752

struct GArgs {
    const __nv_bfloat16 *Ahi, *Alo, *A2hi, *A2lo;
    const float* Xf;
    const __nv_bfloat16 *Whi, *Wlo, *W2hi, *W2lo;
    const float *pb, *pg, *po, *pm, *pv;
    const float *pb2, *pg2, *po2;
    __nv_bfloat16 *Yhi, *Ylo, *Y2hi, *Y2lo;
    const int* idx;
    const float *wf, *wfb;
    float* logits;
    int Kdim, mode, HW, lvl_off, nrows, split;
};

__device__ __forceinline__ void do_chunk(uint32_t sb, int lane, int wm, int wn,
                                         float acc[4][8][4]){
    const int lm_r = (lane & 7) + ((lane >> 3) & 1) * 8;
    const int lm_k = (lane >> 4) * 16;
#pragma unroll
    for (int ks = 0; ks < 4; ks++) {
        const int kb = ks * 32 + lm_k;
        uint32_t ah[4][4], al[4][4];
#pragma unroll
        for (int mi = 0; mi < 4; mi++) {
            int row = wm * 64 + mi * 16 + lm_r;
            uint32_t so = sw128((uint32_t)(row * 128 + kb));
            ldsm4(sb + AH_OFF + so, ah[mi][0], ah[mi][1], ah[mi][2], ah[mi][3]);
            ldsm4(sb + AL_OFF + so, al[mi][0], al[mi][1], al[mi][2], al[mi][3]);
        }
#pragma unroll
        for (int bi = 0; bi < 4; bi++) {
            int nr = wn * 64 + bi * 16 + lm_r;
            uint32_t so = sw128((uint32_t)(nr * 128 + kb));
            uint32_t bh0, bh1, bh2, bh3, bl0, bl1, bl2, bl3;
            ldsm4(sb + BH_OFF + so, bh0, bh1, bh2, bh3);
            ldsm4(sb + BL_OFF + so, bl0, bl1, bl2, bl3);
            // reuse distance of each acc = 8 MMA issues (latency hiding)
#pragma unroll
            for (int mi = 0; mi < 4; mi++) mma_bf16(acc[mi][2*bi],   ah[mi], bh0, bh2);
#pragma unroll
            for (int mi = 0; mi < 4; mi++) mma_bf16(acc[mi][2*bi+1], ah[mi], bh1, bh3);
#pragma unroll
            for (int mi = 0; mi < 4; mi++) mma_bf16(acc[mi][2*bi],   ah[mi], bl0, bl2);
#pragma unroll
            for (int mi = 0; mi < 4; mi++) mma_bf16(acc[mi][2*bi+1], ah[mi], bl1, bl3);
#pragma unroll
            for (int mi = 0; mi < 4; mi++) mma_bf16(acc[mi][2*bi],   al[mi], bh0, bh2);
#pragma unroll
            for (int mi = 0; mi < 4; mi++) mma_bf16(acc[mi][2*bi+1], al[mi], bh1, bh3);
        }
    }
}

// ============================================================================
// tc_gemm
// mode 0: A = bf16 planes [nrows,256], cp.async pipeline. +bias->LN->SiLU
//         (or fused final dot if wf != null)
// mode 1: lateral: A from fp32 [Cin,HW] feature map (sync convert), BN epilogue,
//         token-scattered plane stores.
// mode 2: like mode 0 but A rows gathered via idx (fused gather).
// blockIdx >= split selects the second parameter set (cls/box head pairing).
// ============================================================================
__global__ __launch_bounds__(256) void tc_gemm(GArgs a)
{
    extern __shared__ char smem[];
    const uint32_t sbase = smem_u32(smem);
    const int tid  = threadIdx.x;
    const int lane = tid & 31;
    const int wid  = tid >> 5;
    const int wm   = wid >> 2;
    const int wn   = wid & 3;
    const int mode = a.mode;

    int blk = blockIdx.x;
    const __nv_bfloat16 *Ahi = a.Ahi, *Alo = a.Alo, *Whi = a.Whi, *Wlo = a.Wlo;
    const float *pb = a.pb, *pg = a.pg, *po = a.po;
    __nv_bfloat16 *Yhi = a.Yhi, *Ylo = a.Ylo;
    if (blk >= a.split) {
        blk -= a.split;
        Ahi = a.A2hi; Alo = a.A2lo; Whi = a.W2hi; Wlo = a.W2lo;
        pb = a.pb2; pg = a.pg2; po = a.po2; Yhi = a.Y2hi; Ylo = a.Y2lo;
    }
    const int row0 = blk * 128;

    // params -> smem
    if (mode == 1) {
        float sc = a.pg[tid] * rsqrtf(a.pv[tid] + LN_EPS);
        ((float*)(smem+P_PG))[tid] = sc;
        ((float*)(smem+P_PO))[tid] = a.po[tid] - a.pm[tid] * sc;
    } else {
        ((float*)(smem+P_PB))[tid] = pb[tid];
        ((float*)(smem+P_PG))[tid] = pg[tid];
        ((float*)(smem+P_PO))[tid] = po[tid];
        if (a.wf) ((float*)(smem+P_WF))[tid] = a.wf[tid];
    }
    if (tid < 128) {
        ((float*)(smem+P_RS))[tid] = 0.f;
        ((float*)(smem+P_RQ))[tid] = 0.f;
        ((float*)(smem+P_RD))[tid] = 0.f;
        int i = row0 + tid; if (i >= a.nrows) i = a.nrows - 1;
        int gl = (mode == 2) ? (i / KINST) * NTOK + a.idx[i] : i;
        ((int*)(smem+P_SIDX))[tid] = gl;
    }
    __syncthreads();

    const int* sidx = (const int*)(smem + P_SIDX);
    const int nch = a.Kdim >> 6;

    float acc[4][8][4];
#pragma unroll
    for (int mi = 0; mi < 4; mi++)
#pragma unroll
        for (int ni = 0; ni < 8; ni++)
#pragma unroll
            for (int q = 0; q < 4; q++) acc[mi][ni][q] = 0.f;

    auto issueA = [&](int kc, int stg){
        const int k0 = kc * 64;
        const uint32_t sb = sbase + stg * STAGE;
#pragma unroll
        for (int j = 0; j < 4; j++) {
            int f = tid + j * 256;
            int r = f >> 3, s = f & 7;
            size_t off = (size_t)sidx[r] * 256 + k0 + s * 8;
            uint32_t d = sb + AH_OFF + sw128((uint32_t)(r * 128 + s * 16));
            cpasync16(d, Ahi + off);
            cpasync16(d + (AL_OFF - AH_OFF), Alo + off);
        }
    };
    auto issueB = [&](int kc, int stg){
        const int k0 = kc * 64;
        const uint32_t sb = sbase + stg * STAGE;
#pragma unroll
        for (int j = 0; j < 8; j++) {
            int f = tid + j * 256;
            int o = f >> 3, s = f & 7;
            size_t off = (size_t)o * a.Kdim + k0 + s * 8;
            uint32_t d = sb + BH_OFF + sw128((uint32_t)(o * 128 + s * 16));
            cpasync16(d, Whi + off);
            cpasync16(d + (BL_OFF - BH_OFF), Wlo + off);
        }
    };

    int bb_lat = 0, hw0 = 0;
    if (mode == 1) { bb_lat = row0 / a.HW; hw0 = row0 % a.HW; }

    if (mode != 1) {
        // 2-stage cp.async pipeline
        issueA(0, 0); issueB(0, 0); cp_commit();
        issueA(1, 1); issueB(1, 1); cp_commit();
        for (int kc = 0; kc < nch; kc++) {
            const int stg = kc & 1;
            asm volatile("cp.async.wait_group 1;" ::: "memory");
            __syncthreads();
            do_chunk(sbase + stg * STAGE, lane, wm, wn, acc);
            __syncthreads();
            if (kc + 2 < nch) { issueA(kc + 2, stg); issueB(kc + 2, stg); }
            cp_commit();
        }
    } else {
        for (int kc = 0; kc < nch; kc++) {
            const int k0 = kc * 64;
            issueB(kc, 0); cp_commit();
            // convert A (fp32 feature map, transposed) into stage 0
#pragma unroll
            for (int j = 0; j < 8; j++) {
                int f = tid + j * 256;
                int kk = f >> 5, r4 = (f & 31) * 4;
                float4 v = *(const float4*)(a.Xf + ((size_t)(bb_lat * a.Kdim + k0 + kk)) * a.HW + hw0 + r4);
                float xs[4] = { v.x, v.y, v.z, v.w };
#pragma unroll
                for (int t = 0; t < 4; t++) {
                    __nv_bfloat16 h = __float2bfloat16(xs[t]);
                    __nv_bfloat16 l = __float2bfloat16(xs[t] - __bfloat162float(h));
                    uint32_t so = sw128((uint32_t)((r4 + t) * 128 + kk * 2));
                    *(unsigned short*)(smem + AH_OFF + so) = __bfloat16_as_ushort(h);
                    *(unsigned short*)(smem + AL_OFF + so) = __bfloat16_as_ushort(l);
                }
            }
            asm volatile("cp.async.wait_group 0;" ::: "memory");
            __syncthreads();
            do_chunk(sbase, lane, wm, wn, acc);
            __syncthreads();
        }
    }

    // ---- epilogue ----
    const float* f_bias = (float*)(smem + P_PB);
    const float* f_g    = (float*)(smem + P_PG);
    const float* f_o    = (float*)(smem + P_PO);
    const float* f_wf   = (float*)(smem + P_WF);
    float* rowsum = (float*)(smem + P_RS);
    float* rowsq  = (float*)(smem + P_RQ);
    float* rowdot = (float*)(smem + P_RD);
    const int rloc = lane >> 2;

    if (mode == 1) {
#pragma unroll
        for (int mi = 0; mi < 4; mi++) {
            int rA = wm * 64 + mi * 16 + rloc;
            int rB = rA + 8;
            size_t oA = (size_t)bb_lat * NTOK + a.lvl_off + hw0 + rA;
            size_t oB = oA + 8;
#pragma unroll
            for (int ni = 0; ni < 8; ni++) {
                int c0 = wn * 64 + ni * 8 + (lane & 3) * 2;
                float g0 = f_g[c0], g1 = f_g[c0+1], o0 = f_o[c0], o1 = f_o[c0+1];
                store_hl2(Yhi, Ylo, oA, c0, acc[mi][ni][0]*g0+o0, acc[mi][ni][1]*g1+o1);
                store_hl2(Yhi, Ylo, oB, c0, acc[mi][ni][2]*g0+o0, acc[mi][ni][3]*g1+o1);
            }
        }
        return;
    }

    // mode 0/2: bias add + row stats
#pragma unroll
    for (int mi = 0; mi < 4; mi++) {
        float sA = 0.f, qA = 0.f, sB = 0.f, qB = 0.f;
#pragma unroll
        for (int ni = 0; ni < 8; ni++) {
            int c0 = wn * 64 + ni * 8 + (lane & 3) * 2;
            float b0 = f_bias[c0], b1 = f_bias[c0+1];
            float v0 = acc[mi][ni][0] + b0;
            float v1 = acc[mi][ni][1] + b1;
            float v2 = acc[mi][ni][2] + b0;
            float v3 = acc[mi][ni][3] + b1;
            acc[mi][ni][0]=v0; acc[mi][ni][1]=v1; acc[mi][ni][2]=v2; acc[mi][ni][3]=v3;
            sA += v0 + v1; qA += v0*v0 + v1*v1;
            sB += v2 + v3; qB += v2*v2 + v3*v3;
        }
#pragma unroll
        for (int o = 1; o <= 2; o <<= 1) {
            sA += __shfl_xor_sync(0xffffffffu, sA, o);
            qA += __shfl_xor_sync(0xffffffffu, qA, o);
            sB += __shfl_xor_sync(0xffffffffu, sB, o);
            qB += __shfl_xor_sync(0xffffffffu, qB, o);
        }
        if ((lane & 3) == 0) {
            int rA = wm * 64 + mi * 16 + rloc;
            atomicAdd(&rowsum[rA], sA);   atomicAdd(&rowsq[rA], qA);
            atomicAdd(&rowsum[rA+8], sB); atomicAdd(&rowsq[rA+8], qB);
        }
    }
    __syncthreads();

    if (a.wf) {
        // fused loc final: LN -> SiLU -> dot(Wf)
#pragma unroll
        for (int mi = 0; mi < 4; mi++) {
            int rA = wm * 64 + mi * 16 + rloc;
            int rB = rA + 8;
            float mA = rowsum[rA] * (1.f/256.f);
            float rsA = rsqrtf(rowsq[rA] * (1.f/256.f) - mA*mA + LN_EPS);
            float mB = rowsum[rB] * (1.f/256.f);
            float rsB = rsqrtf(rowsq[rB] * (1.f/256.f) - mB*mB + LN_EPS);
            float pA = 0.f, pB = 0.f;
#pragma unroll
            for (int ni = 0; ni < 8; ni++) {
                int c0 = wn * 64 + ni * 8 + (lane & 3) * 2;
                float g0 = f_g[c0], g1 = f_g[c0+1], o0 = f_o[c0], o1 = f_o[c0+1];
                float u0 = (acc[mi][ni][0] - mA) * rsA * g0 + o0;
                float u1 = (acc[mi][ni][1] - mA) * rsA * g1 + o1;
                float u2 = (acc[mi][ni][2] - mB) * rsB * g0 + o0;
                float u3 = (acc[mi][ni][3] - mB) * rsB * g1 + o1;
                u0 = u0 / (1.f + expf(-u0));
                u1 = u1 / (1.f + expf(-u1));
                u2 = u2 / (1.f + expf(-u2));
                u3 = u3 / (1.f + expf(-u3));
                pA += u0 * f_wf[c0] + u1 * f_wf[c0+1];
                pB += u2 * f_wf[c0] + u3 * f_wf[c0+1];
            }
#pragma unroll
            for (int o = 1; o <= 2; o <<= 1) {
                pA += __shfl_xor_sync(0xffffffffu, pA, o);
                pB += __shfl_xor_sync(0xffffffffu, pB, o);
            }
            if ((lane & 3) == 0) {
                atomicAdd(&rowdot[rA], pA);
                atomicAdd(&rowdot[rB], pB);
            }
        }
        __syncthreads();
        if (tid < 128) {
            int rg = row0 + tid;
            if (rg < a.nrows) a.logits[rg] = rowdot[tid] + a.wfb[0];
        }
    } else {
#pragma unroll
        for (int mi = 0; mi < 4; mi++) {
            int rA = wm * 64 + mi * 16 + rloc;
            int rB = rA + 8;
            float mA = rowsum[rA] * (1.f/256.f);
            float rsA = rsqrtf(rowsq[rA] * (1.f/256.f) - mA*mA + LN_EPS);
            float mB = rowsum[rB] * (1.f/256.f);
            float rsB = rsqrtf(rowsq[rB] * (1.f/256.f) - mB*mB + LN_EPS);
            int rgA = row0 + rA, rgB = row0 + rB;
#pragma unroll
            for (int ni = 0; ni < 8; ni++) {
                int c0 = wn * 64 + ni * 8 + (lane & 3) * 2;
                float g0 = f_g[c0], g1 = f_g[c0+1], o0 = f_o[c0], o1 = f_o[c0+1];
                float u0 = (acc[mi][ni][0] - mA) * rsA * g0 + o0;
                float u1 = (acc[mi][ni][1] - mA) * rsA * g1 + o1;
                float u2 = (acc[mi][ni][2] - mB) * rsB * g0 + o0;
                float u3 = (acc[mi][ni][3] - mB) * rsB * g1 + o1;
                u0 = u0 / (1.f + expf(-u0));
                u1 = u1 / (1.f + expf(-u1));
                u2 = u2 / (1.f + expf(-u2));
                u3 = u3 / (1.f + expf(-u3));
                if (rgA < a.nrows) store_hl2(Yhi, Ylo, (size_t)rgA, c0, u0, u1);
                if (rgB < a.nrows) store_hl2(Yhi, Ylo, (size_t)rgB, c0, u2, u3);
            }
        }
    }
}

// ---------------- weight prep ----------------
__global__ __launch_bounds__(256) void prep_tr(
    const float* __restrict__ locw, const float* __restrict__ clsw,
    const float* __restrict__ boxw, __nv_bfloat16* __restrict__ hi,
    __nv_bfloat16* __restrict__ lo)
{
    int mat = blockIdx.x >> 8;
    int o   = blockIdx.x & 255;
    int k   = threadIdx.x;
    const float* W = (mat < 4 ? locw : (mat < 8 ? clsw : boxw)) + (size_t)(mat & 3) * 65536;
    float v = W[k * 256 + o];
    __nv_bfloat16 h = __float2bfloat16(v);
    size_t oi = (size_t)mat * 65536 + (size_t)o * 256 + k;
    hi[oi] = h;
    lo[oi] = __float2bfloat16(v - __bfloat162float(h));
}

__global__ __launch_bounds__(256) void prep_direct(
    const float* __restrict__ W, __nv_bfloat16* __restrict__ hi,
    __nv_bfloat16* __restrict__ lo, int n)
{
    int i = blockIdx.x * 256 + threadIdx.x;
    if (i < n) {
        float v = W[i];
        __nv_bfloat16 h = __float2bfloat16(v);
        hi[i] = h;
        lo[i] = __float2bfloat16(v - __bfloat162float(h));
    }
}

// ---------------- top-k ----------------
__global__ __launch_bounds__(512) void topk_kernel(
    const float* __restrict__ logits, float* __restrict__ vals, int* __restrict__ idxs)
{
    __shared__ float sv[NTOK];
    __shared__ float rv[16];
    __shared__ int   ri[16];
    const int b = blockIdx.x, tid = threadIdx.x;
    for (int i = tid; i < NTOK; i += 512) sv[i] = logits[b * NTOK + i];
    __syncthreads();
    for (int k = 0; k < KINST; k++) {
        float bv = -3.0e38f; int bi = 0;
        for (int i = tid; i < NTOK; i += 512) {
            float v = sv[i];
            if (v > bv) { bv = v; bi = i; }
        }
#pragma unroll
        for (int o = 16; o > 0; o >>= 1) {
            float ov = __shfl_xor_sync(0xffffffffu, bv, o);
            int   oi = __shfl_xor_sync(0xffffffffu, bi, o);
            if (ov > bv || (ov == bv && oi < bi)) { bv = ov; bi = oi; }
        }
        if ((tid & 31) == 0) { rv[tid >> 5] = bv; ri[tid >> 5] = bi; }
        __syncthreads();
        if (tid == 0) {
            for (int w = 1; w < 16; w++)
                if (rv[w] > bv || (rv[w] == bv && ri[w] < bi)) { bv = rv[w]; bi = ri[w]; }
            vals[b * KINST + k] = bv;
            idxs[b * KINST + k] = bi;
            sv[bi] = -3.3e38f;
        }
        __syncthreads();
    }
}

__device__ __forceinline__ float read_dim(const int* p) {
    int v = p[0];
    if (v > 0 && v < 1000000) return (float)v;
    return __int_as_float(v);
}

// ---------------- merged finals: cls argmax + box decode ----------------
__global__ __launch_bounds__(128) void finals_kernel(
    const __nv_bfloat16* __restrict__ chi, const __nv_bfloat16* __restrict__ clo,
    const __nv_bfloat16* __restrict__ bhi, const __nv_bfloat16* __restrict__ blo,
    const float* __restrict__ clsWf, const float* __restrict__ clsbf,
    const float* __restrict__ boxWf, const float* __restrict__ boxbf,
    const int* __restrict__ idxs, const int* __restrict__ p_fh,
    const int* __restrict__ p_fw, float* __restrict__ out)
{
    __shared__ float xc[256], xb[256], sval[80], e[4];
    int i = blockIdx.x, tid = threadIdx.x, lane = tid & 31, w = tid >> 5;
    {
        size_t base = (size_t)i * 256;
        xc[tid]     = __bfloat162float(chi[base+tid])     + __bfloat162float(clo[base+tid]);
        xc[tid+128] = __bfloat162float(chi[base+tid+128]) + __bfloat162float(clo[base+tid+128]);
        xb[tid]     = __bfloat162float(bhi[base+tid])     + __bfloat162float(blo[base+tid]);
        xb[tid+128] = __bfloat162float(bhi[base+tid+128]) + __bfloat162float(blo[base+tid+128]);
    }
    __syncthreads();
    // box: warp w computes component w
    float s = 0.f;
#pragma unroll
    for (int j = 0; j < 8; j++) {
        int k = lane + j * 32;
        s = fmaf(xb[k], boxWf[k * 4 + w], s);
    }
#pragma unroll
    for (int o = 16; o > 0; o >>= 1) s += __shfl_xor_sync(0xffffffffu, s, o);
    if (lane == 0) e[w] = expf(s + boxbf[w]);
    // cls dots
    if (tid < 80) {
        float s2 = clsbf[tid];
        for (int k = 0; k < 256; k++) s2 = fmaf(xc[k], clsWf[k * 80 + tid], s2);
        sval[tid] = s2;
    }
    __syncthreads();
    if (tid == 0) {
        float bv = sval[0]; int bi = 0;
        for (int t = 1; t < 80; t++) if (sval[t] > bv) { bv = sval[t]; bi = t; }
        out[CL_OFF + i] = (float)bi;

        int n = idxs[i];
        int hsz, m;
        if (n < 4096)      { hsz = 64; m = n; }
        else if (n < 5120) { hsz = 32; m = n - 4096; }
        else               { hsz = 16; m = n - 5120; }
        int gy = m / hsz, gx = m % hsz;
        float inv = 1.0f / (float)hsz;
        float ox = (gx + 0.5f) * inv, oy = (gy + 0.5f) * inv;
        float half = 0.5f * inv;
        float fw = read_dim(p_fw), fh = read_dim(p_fh);
        float* o4 = out + BX_OFF + (size_t)i * 4;
        o4[0] = (ox - half * e[0]) * fw;
        o4[1] = (oy - half * e[1]) * fh;
        o4[2] = (ox + half * e[2]) * fw;
        o4[3] = (oy + half * e[3]) * fh;
    }
}

// ---------------- scores + num_instances ----------------
__global__ __launch_bounds__(800) void scores_kernel(
    const float* __restrict__ vals, float* __restrict__ out)
{
    __shared__ int cnt[BATCH];
    int tid = threadIdx.x;
    if (tid < BATCH) cnt[tid] = 0;
    __syncthreads();
    float v = vals[tid];
    out[SC_OFF + tid] = 1.f / (1.f + expf(-v));
    if (v > 0.f) atomicAdd(&cnt[tid / KINST], 1);
    __syncthreads();
    if (tid < BATCH) out[NI_OFF + tid] = (float)cnt[tid];
}

// ---------------- host launcher ----------------
extern "C" void kernel_launch(void* const* d_in, const int* in_sizes, int n_in,
                              void* d_out, int out_size)
{
    const float* x3     = (const float*)d_in[0];
    const float* x4     = (const float*)d_in[1];
    const float* x5     = (const float*)d_in[2];
    const float* lat_w3 = (const float*)d_in[3];
    const float* lat_w4 = (const float*)d_in[4];
    const float* lat_w5 = (const float*)d_in[5];
    const float* bn_g   = (const float*)d_in[6];
    const float* bn_b   = (const float*)d_in[7];
    const float* bn_m   = (const float*)d_in[8];
    const float* bn_v   = (const float*)d_in[9];
    const float* loc_Ws = (const float*)d_in[10];
    const float* loc_bs = (const float*)d_in[11];
    const float* loc_lng= (const float*)d_in[12];
    const float* loc_lnb= (const float*)d_in[13];
    const float* loc_Wf = (const float*)d_in[14];
    const float* loc_bf = (const float*)d_in[15];
    const float* cls_Ws = (const float*)d_in[16];
    const float* cls_bs = (const float*)d_in[17];
    const float* cls_lng= (const float*)d_in[18];
    const float* cls_lnb= (const float*)d_in[19];
    const float* cls_Wf = (const float*)d_in[20];
    const float* cls_bf = (const float*)d_in[21];
    const float* box_Ws = (const float*)d_in[22];
    const float* box_bs = (const float*)d_in[23];
    const float* box_lng= (const float*)d_in[24];
    const float* box_lnb= (const float*)d_in[25];
    const float* box_Wf = (const float*)d_in[26];
    const float* box_bf = (const float*)d_in[27];
    const int*   p_fh   = (const int*)d_in[28];
    const int*   p_fw   = (const int*)d_in[29];
    float* out = (float*)d_out;

    __nv_bfloat16 *flathi, *flatlo, *p0hi, *p0lo, *p1hi, *p1lo, *hd, *whi, *wlo, *lathi, *latlo;
    float *logits, *vals; int* idxp;
    cudaGetSymbolAddress((void**)&flathi, g_flathi);
    cudaGetSymbolAddress((void**)&flatlo, g_flatlo);
    cudaGetSymbolAddress((void**)&p0hi,   g_p0hi);
    cudaGetSymbolAddress((void**)&p0lo,   g_p0lo);
    cudaGetSymbolAddress((void**)&p1hi,   g_p1hi);
    cudaGetSymbolAddress((void**)&p1lo,   g_p1lo);
    cudaGetSymbolAddress((void**)&logits, g_logits);
    cudaGetSymbolAddress((void**)&vals,   g_vals);
    cudaGetSymbolAddress((void**)&idxp,   g_idx);
    cudaGetSymbolAddress((void**)&hd,     g_hd);
    cudaGetSymbolAddress((void**)&whi,    g_whi);
    cudaGetSymbolAddress((void**)&wlo,    g_wlo);
    cudaGetSymbolAddress((void**)&lathi,  g_lathi);
    cudaGetSymbolAddress((void**)&latlo,  g_latlo);

    const size_t HP = 896 * 256;   // head plane stride
    __nv_bfloat16* c0hi = hd + 0*HP; __nv_bfloat16* c0lo = hd + 1*HP;
    __nv_bfloat16* c1hi = hd + 2*HP; __nv_bfloat16* c1lo = hd + 3*HP;
    __nv_bfloat16* b0hi = hd + 4*HP; __nv_bfloat16* b0lo = hd + 5*HP;
    __nv_bfloat16* b1hi = hd + 6*HP; __nv_bfloat16* b1lo = hd + 7*HP;

    cudaFuncSetAttribute(tc_gemm, cudaFuncAttributeMaxDynamicSharedMemorySize, SMEM_TOTAL);

    // 0) weight prep
    prep_tr<<<12*256, 256>>>(loc_Ws, cls_Ws, box_Ws, whi, wlo);
    prep_direct<<<(65536+255)/256, 256>>>(lat_w3, lathi, latlo, 65536);
    prep_direct<<<(131072+255)/256, 256>>>(lat_w4, lathi + 65536, latlo + 65536, 131072);
    prep_direct<<<(262144+255)/256, 256>>>(lat_w5, lathi + 196608, latlo + 196608, 262144);

    GArgs a; memset(&a, 0, sizeof(a));
    a.split = 1 << 30;

    // 1) laterals -> flat planes (mode 1)
    {
        GArgs L = a; L.mode = 1;
        L.Xf = x3; L.Whi = lathi; L.Wlo = latlo; L.Kdim = 256; L.HW = 4096; L.lvl_off = 0;
        L.pg = bn_g + 0*C; L.po = bn_b + 0*C; L.pm = bn_m + 0*C; L.pv = bn_v + 0*C;
        L.Yhi = flathi; L.Ylo = flatlo; L.nrows = BATCH*4096;
        tc_gemm<<<BATCH*4096/128, 256, SMEM_TOTAL>>>(L);
        L.Xf = x4; L.Whi = lathi + 65536; L.Wlo = latlo + 65536; L.Kdim = 512; L.HW = 1024; L.lvl_off = 4096;
        L.pg = bn_g + 1*C; L.po = bn_b + 1*C; L.pm = bn_m + 1*C; L.pv = bn_v + 1*C;
        L.nrows = BATCH*1024;
        tc_gemm<<<BATCH*1024/128, 256, SMEM_TOTAL>>>(L);
        L.Xf = x5; L.Whi = lathi + 196608; L.Wlo = latlo + 196608; L.Kdim = 1024; L.HW = 256; L.lvl_off = 5120;
        L.pg = bn_g + 2*C; L.po = bn_b + 2*C; L.pm = bn_m + 2*C; L.pv = bn_v + 2*C;
        L.nrows = BATCH*256;
        tc_gemm<<<BATCH*256/128, 256, SMEM_TOTAL>>>(L);
    }

    // 2) loc MLP: 4 layers, layer 4 fused with final dot -> logits
    {
        const __nv_bfloat16* curhi = flathi;
        const __nv_bfloat16* curlo = flatlo;
        __nv_bfloat16* phi[2] = { p0hi, p1hi };
        __nv_bfloat16* plo[2] = { p0lo, p1lo };
        for (int i = 0; i < 4; i++) {
            GArgs L = a; L.mode = 0; L.Kdim = 256; L.nrows = TOT;
            L.Ahi = curhi; L.Alo = curlo;
            L.Whi = whi + (size_t)i*65536; L.Wlo = wlo + (size_t)i*65536;
            L.pb = loc_bs + i*C; L.pg = loc_lng + i*C; L.po = loc_lnb + i*C;
            if (i == 3) { L.wf = loc_Wf; L.wfb = loc_bf; L.logits = logits; }
            else { L.Yhi = phi[i & 1]; L.Ylo = plo[i & 1]; }
            tc_gemm<<<TOT/128, 256, SMEM_TOTAL>>>(L);
            curhi = phi[i & 1]; curlo = plo[i & 1];
        }
    }

    // 3) top-k
    topk_kernel<<<BATCH, 512>>>(logits, vals, idxp);

    // 4) heads: 4 combined cls+box layers (grid 14, split 7); layer 1 = fused gather (mode 2)
    {
        const __nv_bfloat16 *cAhi = flathi, *cAlo = flatlo, *bAhi = flathi, *bAlo = flatlo;
        __nv_bfloat16 *cY[2][2] = { {c0hi, c0lo}, {c1hi, c1lo} };
        __nv_bfloat16 *bY[2][2] = { {b0hi, b0lo}, {b1hi, b1lo} };
        for (int i = 0; i < 4; i++) {
            GArgs L = a; L.mode = (i == 0) ? 2 : 0; L.Kdim = 256; L.nrows = 800; L.split = 7;
            L.idx = idxp;
            L.Ahi = cAhi;  L.Alo = cAlo;
            L.A2hi = bAhi; L.A2lo = bAlo;
            L.Whi  = whi + (size_t)(4+i)*65536; L.Wlo  = wlo + (size_t)(4+i)*65536;
            L.W2hi = whi + (size_t)(8+i)*65536; L.W2lo = wlo + (size_t)(8+i)*65536;
            L.pb = cls_bs + i*C;  L.pg = cls_lng + i*C;  L.po = cls_lnb + i*C;
            L.pb2 = box_bs + i*C; L.pg2 = box_lng + i*C; L.po2 = box_lnb + i*C;
            L.Yhi = cY[i & 1][0];  L.Ylo = cY[i & 1][1];
            L.Y2hi = bY[i & 1][0]; L.Y2lo = bY[i & 1][1];
            tc_gemm<<<14, 256, SMEM_TOTAL>>>(L);
            cAhi = cY[i & 1][0]; cAlo = cY[i & 1][1];
            bAhi = bY[i & 1][0]; bAlo = bY[i & 1][1];
        }
        // layer 4 outputs are in c1/b1 (i=3 -> index 1)
    }

    // 5) finals + scores
    finals_kernel<<<800, 128>>>(c1hi, c1lo, b1hi, b1lo,
        cls_Wf, cls_bf, box_Wf, box_bf, idxp, p_fh, p_fw, out);
    scores_kernel<<<1, 800>>>(vals, out);
}